// round 4
// baseline (speedup 1.0000x reference)
#include <cuda_runtime.h>
#include <cuda_bf16.h>
#include <math.h>
#include <stdint.h>

// ---------------- problem constants ----------------
#define LSEQ   2048
#define DMODEL 1024
#define DINNER 2048
#define DSTATE 16
#define DTRANK 64
#define XDBL   96
#define NEXP   8
#define HIDDEN 4096
#define NPAIR  4096
#define SPLITK 8

// ---------------- fp32 scratch ----------------
__device__ float g_xn   [LSEQ * DMODEL];
__device__ float g_xr   [LSEQ * 2 * DINNER];
__device__ float g_u    [LSEQ * DINNER];
__device__ float g_xdbl [LSEQ * XDBL];
__device__ float g_xp   [SPLITK * LSEQ * XDBL];
__device__ float g_delta[LSEQ * DINNER];
__device__ float g_xm2  [LSEQ * DMODEL];
__device__ float g_xm2n [LSEQ * DMODEL];
__device__ int   g_top_e[LSEQ * 2];
__device__ float g_top_v[LSEQ * 2];
__device__ int   g_cnt[NEXP];
__device__ int   g_cur[NEXP];
__device__ int   g_off[NEXP + 1];
__device__ int   g_ptok[NPAIR];
__device__ float g_pw  [NPAIR];
__device__ int   g_tok_pair[LSEQ * 2];
__device__ float g_y2[(size_t)NPAIR * DMODEL];

// ---------------- bf16 hi/lo scratch ----------------
__device__ __align__(16) __nv_bfloat16 g_xn_h [LSEQ * DMODEL],  g_xn_l [LSEQ * DMODEL];
__device__ __align__(16) __nv_bfloat16 g_xd_h [LSEQ * XDBL],    g_xd_l [LSEQ * XDBL];
__device__ __align__(16) __nv_bfloat16 g_y_h  [LSEQ * DINNER],  g_y_l  [LSEQ * DINNER];
__device__ __align__(16) __nv_bfloat16 g_x2_h [LSEQ * DMODEL],  g_x2_l [LSEQ * DMODEL];
__device__ __align__(16) __nv_bfloat16 g_h_h  [(size_t)NPAIR * HIDDEN], g_h_l [(size_t)NPAIR * HIDDEN];
__device__ __align__(16) __nv_bfloat16 g_wi_h [2 * DINNER * DMODEL], g_wi_l [2 * DINNER * DMODEL];
__device__ __align__(16) __nv_bfloat16 g_wd_h [DINNER * DTRANK],     g_wd_l [DINNER * DTRANK];
__device__ __align__(16) __nv_bfloat16 g_wo_h [DMODEL * DINNER],     g_wo_l [DMODEL * DINNER];
__device__ __align__(16) __nv_bfloat16 g_w1_h [(size_t)NEXP * HIDDEN * DMODEL], g_w1_l [(size_t)NEXP * HIDDEN * DMODEL];
__device__ __align__(16) __nv_bfloat16 g_w2_h [(size_t)NEXP * DMODEL * HIDDEN], g_w2_l [(size_t)NEXP * DMODEL * HIDDEN];

// ---------------- helpers ----------------
__device__ __forceinline__ uint32_t packhl2(float a, float b, uint32_t& lo)
{
    __nv_bfloat162 h, l;
    h.x = __float2bfloat16_rn(a);
    h.y = __float2bfloat16_rn(b);
    l.x = __float2bfloat16_rn(a - __bfloat162float(h.x));
    l.y = __float2bfloat16_rn(b - __bfloat162float(h.y));
    lo = *(uint32_t*)&l;
    return *(uint32_t*)&h;
}

__device__ __forceinline__ void mma16(float* d, const uint32_t* a, const uint32_t* b)
{
    asm volatile(
        "mma.sync.aligned.m16n8k16.row.col.f32.bf16.bf16.f32 "
        "{%0,%1,%2,%3},{%4,%5,%6,%7},{%8,%9},{%0,%1,%2,%3};\n"
        : "+f"(d[0]), "+f"(d[1]), "+f"(d[2]), "+f"(d[3])
        : "r"(a[0]), "r"(a[1]), "r"(a[2]), "r"(a[3]), "r"(b[0]), "r"(b[1]));
}

__device__ __forceinline__ void cpa16(uint32_t dst, const void* src)
{
    asm volatile("cp.async.cg.shared.global [%0], [%1], 16;" :: "r"(dst), "l"(src));
}

// fragment load from swizzled tile: row stride = 16 words, quarter swizzle
__device__ __forceinline__ uint32_t fr(const uint32_t* s, int row, int w)
{
    return s[row * 16 + ((((w >> 2) ^ ((row >> 1) & 3)) << 2) | (w & 3))];
}

// ---------------- weight/activation splitter ----------------
__global__ void split_bf(const float4* __restrict__ src, uint2* __restrict__ hi,
                         uint2* __restrict__ lo, int n4)
{
    int i = blockIdx.x * 256 + threadIdx.x;
    if (i >= n4) return;
    float4 v = src[i];
    uint32_t l0, l1;
    uint32_t h0 = packhl2(v.x, v.y, l0);
    uint32_t h1 = packhl2(v.z, v.w, l1);
    hi[i] = make_uint2(h0, h1);
    lo[i] = make_uint2(l0, l1);
}

// ---------------- bgemm: bf16x2 3-term tensor GEMM, cp.async double-buffered --------
// A pre-split (M,K) bf16 hi/lo row-major stride lda; W pre-split (N,K) stride K.
// EPI: 0 store fp32, 1 gelu->bf16 hi/lo, 2 +addsrc fp32, 3 softplus(+bias) fp32
// MODE: 0 plain, 1 gather rows via ptok + per-expert W, 2 contiguous expert rows
#define STG_W 8192   // words per stage (4 tiles * 2048)
template<int EPI, int MODE>
__global__ void __launch_bounds__(256) bgemm(
    const __nv_bfloat16* __restrict__ Ahi, const __nv_bfloat16* __restrict__ Alo, int lda,
    const __nv_bfloat16* __restrict__ Whi, const __nv_bfloat16* __restrict__ Wlo, int K,
    float* __restrict__ C, int ldc, int M, int N,
    const float* __restrict__ bias,
    const float* __restrict__ addsrc, int ldadd,
    const int* __restrict__ off, const int* __restrict__ ptok,
    __nv_bfloat16* __restrict__ Chi, __nv_bfloat16* __restrict__ Clo)
{
    extern __shared__ uint32_t smem[];
    int base = 0, rows = M;
    const __nv_bfloat16 *Wh = Whi, *Wl = Wlo;
    if (MODE != 0) {
        int e = blockIdx.z;
        base = off[e];
        rows = off[e + 1] - base;
        Wh = Whi + (size_t)e * N * K;
        Wl = Wlo + (size_t)e * N * K;
    }
    int m0 = blockIdx.x * 128;
    if (m0 >= rows) return;
    int n0 = blockIdx.y * 128;

    int tid = threadIdx.x;
    int wid = tid >> 5, lane = tid & 31;
    int lr = lane >> 2, lc = lane & 3;
    int warp_m = wid & 1, warp_n = wid >> 1;

    int arow0 = tid >> 2, arow1 = arow0 + 64;
    int qg = tid & 3;

    // A row pointers (clamped; invalid rows masked in epilogue)
    int r0 = m0 + arow0, r1 = m0 + arow1;
    bool aok0, aok1;
    size_t aoff0, aoff1;
    if (MODE == 1) {
        aok0 = r0 < rows; aok1 = r1 < rows;
        aoff0 = (size_t)(aok0 ? ptok[base + r0] : 0) * lda;
        aoff1 = (size_t)(aok1 ? ptok[base + r1] : 0) * lda;
    } else if (MODE == 2) {
        aok0 = r0 < rows; aok1 = r1 < rows;
        aoff0 = (size_t)(base + (aok0 ? r0 : 0)) * lda;
        aoff1 = (size_t)(base + (aok1 ? r1 : 0)) * lda;
    } else {
        aok0 = true; aok1 = true;
        aoff0 = (size_t)r0 * lda;
        aoff1 = (size_t)r1 * lda;
    }
    const __nv_bfloat16* ah0 = Ahi + aoff0 + qg * 8;
    const __nv_bfloat16* ah1 = Ahi + aoff1 + qg * 8;
    const __nv_bfloat16* al0 = Alo + aoff0 + qg * 8;
    const __nv_bfloat16* al1 = Alo + aoff1 + qg * 8;
    const __nv_bfloat16* bh0 = Wh + (size_t)(n0 + arow0) * K + qg * 8;
    const __nv_bfloat16* bh1 = Wh + (size_t)(n0 + arow1) * K + qg * 8;
    const __nv_bfloat16* bl0 = Wl + (size_t)(n0 + arow0) * K + qg * 8;
    const __nv_bfloat16* bl1 = Wl + (size_t)(n0 + arow1) * K + qg * 8;

    uint32_t sb0 = (uint32_t)__cvta_generic_to_shared(smem);
    int dA0 = (arow0 * 16 + ((qg ^ ((arow0 >> 1) & 3)) << 2)) * 4;   // byte offsets
    int dA1 = (arow1 * 16 + ((qg ^ ((arow1 >> 1) & 3)) << 2)) * 4;

    float acc[4][4][4];
    #pragma unroll
    for (int i = 0; i < 4; i++)
        #pragma unroll
        for (int j = 0; j < 4; j++)
            #pragma unroll
            for (int r = 0; r < 4; r++) acc[i][j][r] = 0.f;

    int nt = K >> 5;
    // prologue: tile 0 into stage 0
    {
        uint32_t sb = sb0;
        cpa16(sb + 0 * 8192 + dA0, ah0);
        cpa16(sb + 0 * 8192 + dA1, ah1);
        cpa16(sb + 1 * 8192 + dA0, al0);
        cpa16(sb + 1 * 8192 + dA1, al1);
        cpa16(sb + 2 * 8192 + dA0, bh0);
        cpa16(sb + 2 * 8192 + dA1, bh1);
        cpa16(sb + 3 * 8192 + dA0, bl0);
        cpa16(sb + 3 * 8192 + dA1, bl1);
        asm volatile("cp.async.commit_group;");
    }
    for (int t = 0; t < nt; t++) {
        __syncthreads();   // buffer (t+1)&1 no longer being read
        if (t + 1 < nt) {
            int kt = (t + 1) << 5;
            uint32_t sb = sb0 + ((t + 1) & 1) * (STG_W * 4);
            cpa16(sb + 0 * 8192 + dA0, ah0 + kt);
            cpa16(sb + 0 * 8192 + dA1, ah1 + kt);
            cpa16(sb + 1 * 8192 + dA0, al0 + kt);
            cpa16(sb + 1 * 8192 + dA1, al1 + kt);
            cpa16(sb + 2 * 8192 + dA0, bh0 + kt);
            cpa16(sb + 2 * 8192 + dA1, bh1 + kt);
            cpa16(sb + 3 * 8192 + dA0, bl0 + kt);
            cpa16(sb + 3 * 8192 + dA1, bl1 + kt);
        }
        asm volatile("cp.async.commit_group;");
        asm volatile("cp.async.wait_group 1;");
        __syncthreads();

        const uint32_t* S = smem + (t & 1) * STG_W;
        const uint32_t* sAh = S;
        const uint32_t* sAl = S + 2048;
        const uint32_t* sBh = S + 4096;
        const uint32_t* sBl = S + 6144;

        #pragma unroll
        for (int sub = 0; sub < 2; sub++) {
            int w0 = sub * 8 + lc, w1 = w0 + 4;
            uint32_t bh[4][2], bl[4][2];
            #pragma unroll
            for (int in = 0; in < 4; in++) {
                int n = warp_n * 32 + in * 8 + lr;
                bh[in][0] = fr(sBh, n, w0); bh[in][1] = fr(sBh, n, w1);
                bl[in][0] = fr(sBl, n, w0); bl[in][1] = fr(sBl, n, w1);
            }
            #pragma unroll
            for (int im = 0; im < 4; im++) {
                int m = warp_m * 64 + im * 16 + lr;
                uint32_t ah[4] = { fr(sAh, m, w0), fr(sAh, m + 8, w0),
                                   fr(sAh, m, w1), fr(sAh, m + 8, w1) };
                uint32_t al[4] = { fr(sAl, m, w0), fr(sAl, m + 8, w0),
                                   fr(sAl, m, w1), fr(sAl, m + 8, w1) };
                #pragma unroll
                for (int in = 0; in < 4; in++) {
                    mma16(acc[im][in], ah, bh[in]);
                    mma16(acc[im][in], ah, bl[in]);
                    mma16(acc[im][in], al, bh[in]);
                }
            }
        }
    }

    // epilogue
    #pragma unroll
    for (int im = 0; im < 4; im++) {
        #pragma unroll
        for (int half = 0; half < 2; half++) {
            int m = m0 + warp_m * 64 + im * 16 + lr + half * 8;
            if (m >= rows) continue;
            size_t crow = (size_t)(base + m) * ldc;
            #pragma unroll
            for (int in = 0; in < 4; in++) {
                int n = n0 + warp_n * 32 + in * 8 + lc * 2;
                float v0 = acc[im][in][half * 2];
                float v1 = acc[im][in][half * 2 + 1];
                if (EPI == 1) {
                    v0 = 0.5f * v0 * (1.0f + erff(v0 * 0.70710678118654752f));
                    v1 = 0.5f * v1 * (1.0f + erff(v1 * 0.70710678118654752f));
                    uint32_t lp;
                    uint32_t hp = packhl2(v0, v1, lp);
                    *(uint32_t*)(Chi + crow + n) = hp;
                    *(uint32_t*)(Clo + crow + n) = lp;
                } else {
                    if (EPI == 2) {
                        v0 += addsrc[(size_t)m * ldadd + n];
                        v1 += addsrc[(size_t)m * ldadd + n + 1];
                    } else if (EPI == 3) {
                        float z0 = v0 + bias[n], z1 = v1 + bias[n + 1];
                        v0 = (z0 > 20.f) ? z0 : log1pf(__expf(z0));
                        v1 = (z1 > 20.f) ? z1 : log1pf(__expf(z1));
                    }
                    *(float2*)(C + crow + n) = make_float2(v0, v1);
                }
            }
        }
    }
}

// ---------------- rmsnorm (optionally writes bf16 hi/lo too) ----------------
template<bool WS>
__global__ void rmsnorm_kernel(const float* __restrict__ x, float* __restrict__ o,
                               __nv_bfloat16* __restrict__ oh, __nv_bfloat16* __restrict__ ol)
{
    int row = blockIdx.x;
    const float* xp = x + (size_t)row * DMODEL;
    float s = 0.f;
    for (int k = threadIdx.x; k < DMODEL; k += 256) { float v = xp[k]; s += v * v; }
    __shared__ float sh[8];
    #pragma unroll
    for (int off = 16; off; off >>= 1) s += __shfl_xor_sync(0xffffffffu, s, off);
    if ((threadIdx.x & 31) == 0) sh[threadIdx.x >> 5] = s;
    __syncthreads();
    if (threadIdx.x < 8) {
        float v = sh[threadIdx.x];
        #pragma unroll
        for (int off = 4; off; off >>= 1) v += __shfl_xor_sync(0xffu, v, off);
        if (threadIdx.x == 0) sh[0] = v;
    }
    __syncthreads();
    float scale = 32.0f / fmaxf(sqrtf(sh[0]), 1e-12f);
    size_t rb = (size_t)row * DMODEL;
    for (int k = threadIdx.x; k < DMODEL; k += 256) {
        float v = xp[k] * scale;
        o[rb + k] = v;
        if (WS) {
            __nv_bfloat16 h = __float2bfloat16_rn(v);
            oh[rb + k] = h;
            ol[rb + k] = __float2bfloat16_rn(v - __bfloat162float(h));
        }
    }
}

// ---------------- split-K SIMT GEMM for skinny x_proj ----------------
__global__ void __launch_bounds__(256) gemm_sk(
    const float* __restrict__ A, int lda,
    const float* __restrict__ W, int ldw,
    float* __restrict__ Cpart, int ldc,
    int M, int N, int kchunk)
{
    int koff = blockIdx.z * kchunk;
    float* C = Cpart + (size_t)blockIdx.z * M * ldc;
    __shared__ float As[16][68];
    __shared__ float Bs[16][68];
    int tid = threadIdx.x;
    int m0 = blockIdx.x * 64, n0 = blockIdx.y * 64;
    int tx = tid & 15, ty = tid >> 4;
    int lr = tid >> 2;
    int lk = (tid & 3) << 2;
    int am = m0 + lr;
    int wn = n0 + lr;
    bool a_ok = am < M;
    bool w_ok = wn < N;
    const float* Arow = A + (size_t)(a_ok ? am : 0) * lda + koff;
    const float* Wrow = W + (size_t)(w_ok ? wn : 0) * ldw + koff;
    float acc[4][4] = {};
    for (int k0 = 0; k0 < kchunk; k0 += 16) {
        float4 av = a_ok ? *(const float4*)(Arow + k0 + lk) : make_float4(0, 0, 0, 0);
        float4 wv = w_ok ? *(const float4*)(Wrow + k0 + lk) : make_float4(0, 0, 0, 0);
        __syncthreads();
        As[lk][lr] = av.x; As[lk + 1][lr] = av.y; As[lk + 2][lr] = av.z; As[lk + 3][lr] = av.w;
        Bs[lk][lr] = wv.x; Bs[lk + 1][lr] = wv.y; Bs[lk + 2][lr] = wv.z; Bs[lk + 3][lr] = wv.w;
        __syncthreads();
        #pragma unroll
        for (int k = 0; k < 16; k++) {
            float a[4], b[4];
            #pragma unroll
            for (int i = 0; i < 4; i++) a[i] = As[k][ty * 4 + i];
            #pragma unroll
            for (int j = 0; j < 4; j++) b[j] = Bs[k][tx * 4 + j];
            #pragma unroll
            for (int i = 0; i < 4; i++)
                #pragma unroll
                for (int j = 0; j < 4; j++)
                    acc[i][j] += a[i] * b[j];
        }
    }
    #pragma unroll
    for (int i = 0; i < 4; i++) {
        int m = m0 + ty * 4 + i;
        if (m >= M) continue;
        #pragma unroll
        for (int j = 0; j < 4; j++) {
            int n = n0 + tx * 4 + j;
            if (n >= N) continue;
            C[(size_t)m * ldc + n] = acc[i][j];
        }
    }
}

__global__ void reduce_sk(const float* __restrict__ p, float* __restrict__ o,
                          __nv_bfloat16* __restrict__ oh, __nv_bfloat16* __restrict__ ol, int n)
{
    int i = blockIdx.x * 256 + threadIdx.x;
    if (i >= n) return;
    float s = 0.f;
    #pragma unroll
    for (int j = 0; j < SPLITK; j++) s += p[i + (size_t)j * n];
    o[i] = s;
    __nv_bfloat16 h = __float2bfloat16_rn(s);
    oh[i] = h;
    ol[i] = __float2bfloat16_rn(s - __bfloat162float(h));
}

// ---------------- causal depthwise conv(4) + silu ----------------
__global__ void conv_silu(const float* __restrict__ xr, const float* __restrict__ cw,
                          const float* __restrict__ cb, float* __restrict__ u)
{
    int idx = blockIdx.x * 256 + threadIdx.x;
    int t = idx >> 11, d = idx & (DINNER - 1);
    float w0 = cw[d * 4], w1 = cw[d * 4 + 1], w2 = cw[d * 4 + 2], w3 = cw[d * 4 + 3];
    float s = cb[d];
    const float* col = xr + d;
    if (t >= 3) s += col[(size_t)(t - 3) * (2 * DINNER)] * w0;
    if (t >= 2) s += col[(size_t)(t - 2) * (2 * DINNER)] * w1;
    if (t >= 1) s += col[(size_t)(t - 1) * (2 * DINNER)] * w2;
    s += col[(size_t)t * (2 * DINNER)] * w3;
    u[idx] = s / (1.f + __expf(-s));
}

// ---------------- selective scan (writes y bf16 hi/lo) ----------------
__global__ void scan_kernel(const float* __restrict__ delta,
                            const float* __restrict__ u,
                            const float* __restrict__ xdbl,
                            const float* __restrict__ A_log,
                            const float* __restrict__ Dvec,
                            const float* __restrict__ xr,
                            __nv_bfloat16* __restrict__ yh,
                            __nv_bfloat16* __restrict__ yl)
{
    int lane16 = threadIdx.x & 15;
    int ch = threadIdx.x >> 4;
    int d = blockIdx.x * 8 + ch;
    float A = -__expf(A_log[d * DSTATE + lane16]);
    float Dd = Dvec[d];
    float h = 0.f;
    __shared__ float sB[32][16], sC[32][16], sdl[32][8], su[32][8], sre[32][8];
    for (int t0 = 0; t0 < LSEQ; t0 += 32) {
        __syncthreads();
        for (int i = threadIdx.x; i < 512; i += 128) {
            int tt = i >> 4, n = i & 15;
            const float* xb = xdbl + (size_t)(t0 + tt) * XDBL;
            sB[tt][n] = xb[DTRANK + n];
            sC[tt][n] = xb[DTRANK + DSTATE + n];
        }
        for (int i = threadIdx.x; i < 256; i += 128) {
            int tt = i >> 3, c = i & 7;
            int dd = blockIdx.x * 8 + c;
            size_t off = (size_t)(t0 + tt) * DINNER + dd;
            sdl[tt][c] = delta[off];
            su[tt][c]  = u[off];
            sre[tt][c] = xr[(size_t)(t0 + tt) * (2 * DINNER) + DINNER + dd];
        }
        __syncthreads();
        for (int tt = 0; tt < 32; tt++) {
            float dl = sdl[tt][ch];
            float uu = su[tt][ch];
            float dA = __expf(dl * A);
            h = dA * h + dl * sB[tt][lane16] * uu;
            float p = h * sC[tt][lane16];
            #pragma unroll
            for (int o = 8; o; o >>= 1) p += __shfl_xor_sync(0xffffffffu, p, o, 16);
            if (lane16 == 0) {
                float yv = p + uu * Dd;
                float r = sre[tt][ch];
                yv *= r / (1.f + __expf(-r));
                size_t idx = (size_t)(t0 + tt) * DINNER + d;
                __nv_bfloat16 hb = __float2bfloat16_rn(yv);
                yh[idx] = hb;
                yl[idx] = __float2bfloat16_rn(yv - __bfloat162float(hb));
            }
        }
    }
}

// ---------------- gating: GEMV + softmax + top-2 ----------------
__global__ void gate_topk(const float* __restrict__ X, const float* __restrict__ gw,
                          int* __restrict__ te, float* __restrict__ tv)
{
    __shared__ float sg[NEXP * DMODEL];
    for (int i = threadIdx.x; i < NEXP * DMODEL; i += 128) sg[i] = gw[i];
    __syncthreads();
    int warp = threadIdx.x >> 5, lane = threadIdx.x & 31;
    int t = blockIdx.x * 4 + warp;
    const float* xp = X + (size_t)t * DMODEL;
    float acc[NEXP] = {};
    for (int k = lane; k < DMODEL; k += 32) {
        float xv = xp[k];
        #pragma unroll
        for (int e = 0; e < NEXP; e++) acc[e] += xv * sg[e * DMODEL + k];
    }
    #pragma unroll
    for (int e = 0; e < NEXP; e++)
        #pragma unroll
        for (int o = 16; o; o >>= 1) acc[e] += __shfl_xor_sync(0xffffffffu, acc[e], o);
    if (lane == 0) {
        float m = acc[0];
        #pragma unroll
        for (int e = 1; e < NEXP; e++) m = fmaxf(m, acc[e]);
        float g[NEXP];
        #pragma unroll
        for (int e = 0; e < NEXP; e++) g[e] = __expf(acc[e] - m);
        int i0 = 0;
        #pragma unroll
        for (int e = 1; e < NEXP; e++) if (g[e] > g[i0]) i0 = e;
        int i1 = (i0 == 0) ? 1 : 0;
        #pragma unroll
        for (int e = 0; e < NEXP; e++) if (e != i0 && g[e] > g[i1]) i1 = e;
        float inv = 1.f / (g[i0] + g[i1]);
        te[t * 2] = i0; te[t * 2 + 1] = i1;
        tv[t * 2] = g[i0] * inv; tv[t * 2 + 1] = g[i1] * inv;
    }
}

// ---------------- routing ----------------
__global__ void route_zero(int* cnt, int* cur)
{
    if (threadIdx.x < NEXP) { cnt[threadIdx.x] = 0; cur[threadIdx.x] = 0; }
}
__global__ void route_count(const int* __restrict__ te, int* cnt)
{
    int t = blockIdx.x * 256 + threadIdx.x;
    atomicAdd(&cnt[te[t * 2]], 1);
    atomicAdd(&cnt[te[t * 2 + 1]], 1);
}
__global__ void route_offsets(const int* __restrict__ cnt, int* off)
{
    int s = 0;
    for (int e = 0; e < NEXP; e++) { off[e] = s; s += cnt[e]; }
    off[NEXP] = s;
}
__global__ void route_scatter(const int* __restrict__ te, const float* __restrict__ tv,
                              const int* __restrict__ off, int* cur,
                              int* ptok, float* pw, int* tok_pair)
{
    int t = blockIdx.x * 256 + threadIdx.x;
    #pragma unroll
    for (int k = 0; k < 2; k++) {
        int e = te[t * 2 + k];
        int pos = atomicAdd(&cur[e], 1);
        int p = off[e] + pos;
        ptok[p] = t;
        pw[p] = tv[t * 2 + k];
        tok_pair[t * 2 + k] = p;
    }
}

// ---------------- final combine ----------------
__global__ void moe_combine(const float* __restrict__ x, const float* __restrict__ y2,
                            const int* __restrict__ tok_pair, const float* __restrict__ pw,
                            float* __restrict__ out)
{
    int i = blockIdx.x * 256 + threadIdx.x;
    int t = i >> 10, n = i & (DMODEL - 1);
    int p0 = tok_pair[t * 2], p1 = tok_pair[t * 2 + 1];
    out[i] = x[i] + pw[p0] * y2[(size_t)p0 * DMODEL + n]
                  + pw[p1] * y2[(size_t)p1 * DMODEL + n];
}

// ---------------- launch ----------------
extern "C" void kernel_launch(void* const* d_in, const int* in_sizes, int n_in,
                              void* d_out, int out_size)
{
    (void)in_sizes; (void)n_in; (void)out_size;
    const float* x          = (const float*)d_in[0];
    const float* in_proj_w  = (const float*)d_in[1];
    const float* conv_w     = (const float*)d_in[2];
    const float* conv_b     = (const float*)d_in[3];
    const float* x_proj_w   = (const float*)d_in[4];
    const float* dt_proj_w  = (const float*)d_in[5];
    const float* dt_proj_b  = (const float*)d_in[6];
    const float* A_log      = (const float*)d_in[7];
    const float* Dvec       = (const float*)d_in[8];
    const float* out_proj_w = (const float*)d_in[9];
    const float* gate_w     = (const float*)d_in[10];
    const float* w1         = (const float*)d_in[11];
    const float* w2         = (const float*)d_in[12];
    float* out = (float*)d_out;

    float *p_xn, *p_xr, *p_u, *p_xdbl, *p_xp, *p_delta, *p_xm2, *p_xm2n, *p_tv, *p_pw, *p_y2;
    int *p_te, *p_cnt, *p_cur, *p_off, *p_ptok, *p_tp;
    __nv_bfloat16 *xn_h, *xn_l, *xd_h, *xd_l, *y_h, *y_l, *x2_h, *x2_l, *h_h, *h_l;
    __nv_bfloat16 *wi_h, *wi_l, *wd_h, *wd_l, *wo_h, *wo_l, *w1_h, *w1_l, *w2_h, *w2_l;
    cudaGetSymbolAddress((void**)&p_xn, g_xn);
    cudaGetSymbolAddress((void**)&p_xr, g_xr);
    cudaGetSymbolAddress((void**)&p_u, g_u);
    cudaGetSymbolAddress((void**)&p_xdbl, g_xdbl);
    cudaGetSymbolAddress((void**)&p_xp, g_xp);
    cudaGetSymbolAddress((void**)&p_delta, g_delta);
    cudaGetSymbolAddress((void**)&p_xm2, g_xm2);
    cudaGetSymbolAddress((void**)&p_xm2n, g_xm2n);
    cudaGetSymbolAddress((void**)&p_te, g_top_e);
    cudaGetSymbolAddress((void**)&p_tv, g_top_v);
    cudaGetSymbolAddress((void**)&p_cnt, g_cnt);
    cudaGetSymbolAddress((void**)&p_cur, g_cur);
    cudaGetSymbolAddress((void**)&p_off, g_off);
    cudaGetSymbolAddress((void**)&p_ptok, g_ptok);
    cudaGetSymbolAddress((void**)&p_pw, g_pw);
    cudaGetSymbolAddress((void**)&p_tp, g_tok_pair);
    cudaGetSymbolAddress((void**)&p_y2, g_y2);
    cudaGetSymbolAddress((void**)&xn_h, g_xn_h); cudaGetSymbolAddress((void**)&xn_l, g_xn_l);
    cudaGetSymbolAddress((void**)&xd_h, g_xd_h); cudaGetSymbolAddress((void**)&xd_l, g_xd_l);
    cudaGetSymbolAddress((void**)&y_h,  g_y_h);  cudaGetSymbolAddress((void**)&y_l,  g_y_l);
    cudaGetSymbolAddress((void**)&x2_h, g_x2_h); cudaGetSymbolAddress((void**)&x2_l, g_x2_l);
    cudaGetSymbolAddress((void**)&h_h,  g_h_h);  cudaGetSymbolAddress((void**)&h_l,  g_h_l);
    cudaGetSymbolAddress((void**)&wi_h, g_wi_h); cudaGetSymbolAddress((void**)&wi_l, g_wi_l);
    cudaGetSymbolAddress((void**)&wd_h, g_wd_h); cudaGetSymbolAddress((void**)&wd_l, g_wd_l);
    cudaGetSymbolAddress((void**)&wo_h, g_wo_h); cudaGetSymbolAddress((void**)&wo_l, g_wo_l);
    cudaGetSymbolAddress((void**)&w1_h, g_w1_h); cudaGetSymbolAddress((void**)&w1_l, g_w1_l);
    cudaGetSymbolAddress((void**)&w2_h, g_w2_h); cudaGetSymbolAddress((void**)&w2_l, g_w2_l);

    const int SMEM = 2 * STG_W * 4;   // 64 KB
    cudaFuncSetAttribute(bgemm<0, 0>, cudaFuncAttributeMaxDynamicSharedMemorySize, SMEM);
    cudaFuncSetAttribute(bgemm<2, 0>, cudaFuncAttributeMaxDynamicSharedMemorySize, SMEM);
    cudaFuncSetAttribute(bgemm<3, 0>, cudaFuncAttributeMaxDynamicSharedMemorySize, SMEM);
    cudaFuncSetAttribute(bgemm<1, 1>, cudaFuncAttributeMaxDynamicSharedMemorySize, SMEM);
    cudaFuncSetAttribute(bgemm<0, 2>, cudaFuncAttributeMaxDynamicSharedMemorySize, SMEM);

    // 0. split weights to bf16 hi/lo
    split_bf<<<(2 * DINNER * DMODEL / 4 + 255) / 256, 256>>>((const float4*)in_proj_w, (uint2*)wi_h, (uint2*)wi_l, 2 * DINNER * DMODEL / 4);
    split_bf<<<(DINNER * DTRANK / 4 + 255) / 256, 256>>>((const float4*)dt_proj_w, (uint2*)wd_h, (uint2*)wd_l, DINNER * DTRANK / 4);
    split_bf<<<(DMODEL * DINNER / 4 + 255) / 256, 256>>>((const float4*)out_proj_w, (uint2*)wo_h, (uint2*)wo_l, DMODEL * DINNER / 4);
    split_bf<<<(int)((size_t)NEXP * HIDDEN * DMODEL / 4 + 255) / 256, 256>>>((const float4*)w1, (uint2*)w1_h, (uint2*)w1_l, NEXP * HIDDEN * DMODEL / 4);
    split_bf<<<(int)((size_t)NEXP * DMODEL * HIDDEN / 4 + 255) / 256, 256>>>((const float4*)w2, (uint2*)w2_h, (uint2*)w2_l, NEXP * DMODEL * HIDDEN / 4);

    // 1. xn = rmsnorm(x) (+ bf16 split)
    rmsnorm_kernel<true><<<LSEQ, 256>>>(x, p_xn, xn_h, xn_l);
    // 2. xr = xn @ in_proj^T  (2048x4096, K=1024)
    bgemm<0, 0><<<dim3(16, 32), 256, SMEM>>>(xn_h, xn_l, DMODEL, wi_h, wi_l, DMODEL,
                                             p_xr, 2 * DINNER, LSEQ, 2 * DINNER,
                                             nullptr, nullptr, 0, nullptr, nullptr, nullptr, nullptr);
    // 3. conv + silu
    conv_silu<<<(LSEQ * DINNER) / 256, 256>>>(p_xr, conv_w, conv_b, p_u);
    // 4. x_dbl = u @ x_proj^T  (2048x96, K=2048) split-K=8 exact
    gemm_sk<<<dim3(32, 2, SPLITK), 256>>>(p_u, DINNER, x_proj_w, DINNER,
                                          p_xp, XDBL, LSEQ, XDBL, DINNER / SPLITK);
    reduce_sk<<<(LSEQ * XDBL + 255) / 256, 256>>>(p_xp, p_xdbl, xd_h, xd_l, LSEQ * XDBL);
    // 5. delta = softplus(dt @ dt_proj^T + b)  (2048x2048, K=64)
    bgemm<3, 0><<<dim3(16, 16), 256, SMEM>>>(xd_h, xd_l, XDBL, wd_h, wd_l, DTRANK,
                                             p_delta, DINNER, LSEQ, DINNER,
                                             dt_proj_b, nullptr, 0, nullptr, nullptr, nullptr, nullptr);
    // 6. selective scan -> y (bf16 hi/lo)
    scan_kernel<<<DINNER / 8, 128>>>(p_delta, p_u, p_xdbl, A_log, Dvec, p_xr, y_h, y_l);
    // 7. xm2 = y @ out_proj^T + xn  (2048x1024, K=2048)
    bgemm<2, 0><<<dim3(16, 8), 256, SMEM>>>(y_h, y_l, DINNER, wo_h, wo_l, DINNER,
                                            p_xm2, DMODEL, LSEQ, DMODEL,
                                            nullptr, p_xn, DMODEL, nullptr, nullptr, nullptr, nullptr);
    // 8. xm2n = rmsnorm(xm2) (+ bf16 split)
    rmsnorm_kernel<true><<<LSEQ, 256>>>(p_xm2, p_xm2n, x2_h, x2_l);
    // 9. gating + routing
    gate_topk<<<LSEQ / 4, 128>>>(p_xm2n, gate_w, p_te, p_tv);
    route_zero<<<1, 32>>>(p_cnt, p_cur);
    route_count<<<LSEQ / 256, 256>>>(p_te, p_cnt);
    route_offsets<<<1, 1>>>(p_cnt, p_off);
    route_scatter<<<LSEQ / 256, 256>>>(p_te, p_tv, p_off, p_cur, p_ptok, p_pw, p_tp);
    // 10. expert GEMMs
    bgemm<1, 1><<<dim3(32, 32, NEXP), 256, SMEM>>>(x2_h, x2_l, DMODEL, w1_h, w1_l, DMODEL,
                                                   nullptr, HIDDEN, 0, HIDDEN,
                                                   nullptr, nullptr, 0, p_off, p_ptok, h_h, h_l);
    bgemm<0, 2><<<dim3(32, 8, NEXP), 256, SMEM>>>(h_h, h_l, HIDDEN, w2_h, w2_l, HIDDEN,
                                                  p_y2, DMODEL, 0, DMODEL,
                                                  nullptr, nullptr, 0, p_off, nullptr, nullptr, nullptr);
    moe_combine<<<(LSEQ * DMODEL) / 256, 256>>>(x, p_y2, p_tp, p_pw, out);
}